// round 14
// baseline (speedup 1.0000x reference)
#include <cuda_runtime.h>
#include <cuda_bf16.h>
#include <math.h>
#include <stdint.h>

// Problem constants
#define NB   4
#define TT   2048
#define DD   1024
#define HH   16
#define DHD  64
#define BT   (NB * TT)          // 8192 rows
#define D3   (3 * DD)           // 3072

// ---------------------------------------------------------------------------
// Scratch (no cudaMalloc allowed — device globals)
// ---------------------------------------------------------------------------
__device__ __nv_bfloat16 g_qh[BT * D3], g_ql[BT * D3];     // QKV bf16 hi/lo
__device__ __nv_bfloat16 g_xnh[BT * DD], g_xnl[BT * DD];   // LN output hi/lo
__device__ __nv_bfloat16 g_wqh[D3 * DD], g_wql[D3 * DD];   // W_qkv hi/lo
__device__ __nv_bfloat16 g_woh[DD * DD], g_wol[DD * DD];   // W_o hi/lo
__device__ __nv_bfloat16 g_cxh[BT * DD], g_cxl[BT * DD];   // ctx hi/lo (attn out)

// ---------------------------------------------------------------------------
// PTX helpers
// ---------------------------------------------------------------------------
#define MMA16816(Cacc, Afrag, Bfrag) \
    asm volatile( \
        "mma.sync.aligned.m16n8k16.row.col.f32.bf16.bf16.f32 " \
        "{%0,%1,%2,%3}, {%4,%5,%6,%7}, {%8,%9}, {%0,%1,%2,%3};" \
        : "+f"((Cacc)[0]), "+f"((Cacc)[1]), "+f"((Cacc)[2]), "+f"((Cacc)[3]) \
        : "r"((Afrag)[0]), "r"((Afrag)[1]), "r"((Afrag)[2]), "r"((Afrag)[3]), \
          "r"((Bfrag)[0]), "r"((Bfrag)[1]))

#define CP16(saddr, gptr) \
    asm volatile("cp.async.cg.shared.global [%0], [%1], 16;" :: "r"(saddr), "l"(gptr))
#define CP_COMMIT() asm volatile("cp.async.commit_group;" ::: "memory")

#define LDSM_X4(r, a) \
    asm volatile("ldmatrix.sync.aligned.m8n8.x4.shared.b16 {%0,%1,%2,%3}, [%4];" \
                 : "=r"((r)[0]), "=r"((r)[1]), "=r"((r)[2]), "=r"((r)[3]) : "r"(a))

#define LDSMT_X2(r, a) \
    asm volatile("ldmatrix.sync.aligned.m8n8.x2.trans.shared.b16 {%0,%1}, [%2];" \
                 : "=r"((r)[0]), "=r"((r)[1]) : "r"(a))

__device__ __forceinline__ uint32_t sptr(const void* p) {
    return (uint32_t)__cvta_generic_to_shared(p);
}

__device__ __forceinline__ void split2(float a, float b, uint32_t& hi, uint32_t& lo) {
    __nv_bfloat16 ha = __float2bfloat16(a), hb = __float2bfloat16(b);
    __nv_bfloat16 la = __float2bfloat16(a - __bfloat162float(ha));
    __nv_bfloat16 lb = __float2bfloat16(b - __bfloat162float(hb));
    __nv_bfloat162 th = __halves2bfloat162(ha, hb);
    __nv_bfloat162 tl = __halves2bfloat162(la, lb);
    hi = *reinterpret_cast<uint32_t*>(&th);
    lo = *reinterpret_cast<uint32_t*>(&tl);
}

// ---------------------------------------------------------------------------
// LayerNorm: one block (256 threads) per row; writes bf16 hi/lo split
// ---------------------------------------------------------------------------
__global__ void __launch_bounds__(256) ln_kernel(const float* __restrict__ x,
                                                 const float* __restrict__ gamma,
                                                 const float* __restrict__ beta) {
    int row = blockIdx.x;
    int tid = threadIdx.x;
    __shared__ float red[2][8];

    const float4* xr = (const float4*)(x + (size_t)row * DD);
    float4 xv = xr[tid];
    float s  = xv.x + xv.y + xv.z + xv.w;
    float s2 = xv.x * xv.x + xv.y * xv.y + xv.z * xv.z + xv.w * xv.w;

    #pragma unroll
    for (int o = 16; o > 0; o >>= 1) {
        s  += __shfl_xor_sync(0xffffffffu, s, o);
        s2 += __shfl_xor_sync(0xffffffffu, s2, o);
    }
    if ((tid & 31) == 0) { red[0][tid >> 5] = s; red[1][tid >> 5] = s2; }
    __syncthreads();
    if (tid < 32) {
        float a = (tid < 8) ? red[0][tid] : 0.f;
        float b = (tid < 8) ? red[1][tid] : 0.f;
        #pragma unroll
        for (int o = 4; o > 0; o >>= 1) {
            a += __shfl_xor_sync(0xffffffffu, a, o);
            b += __shfl_xor_sync(0xffffffffu, b, o);
        }
        if (tid == 0) { red[0][0] = a * (1.f / DD); red[1][0] = b * (1.f / DD); }
    }
    __syncthreads();

    float mu   = red[0][0];
    float var  = red[1][0] - mu * mu;
    float rstd = rsqrtf(var + 1e-5f);

    float4 g  = ((const float4*)gamma)[tid];
    float4 bb = ((const float4*)beta)[tid];
    float y[4];
    y[0] = (xv.x - mu) * rstd * g.x + bb.x;
    y[1] = (xv.y - mu) * rstd * g.y + bb.y;
    y[2] = (xv.z - mu) * rstd * g.z + bb.z;
    y[3] = (xv.w - mu) * rstd * g.w + bb.w;

    size_t base = (size_t)row * DD + tid * 4;
    uint32_t h01, l01, h23, l23;
    split2(y[0], y[1], h01, l01);
    split2(y[2], y[3], h23, l23);
    ((uint32_t*)(g_xnh + base))[0] = h01;
    ((uint32_t*)(g_xnh + base))[1] = h23;
    ((uint32_t*)(g_xnl + base))[0] = l01;
    ((uint32_t*)(g_xnl + base))[1] = l23;
}

// ---------------------------------------------------------------------------
// fp32 -> bf16 hi/lo split convert (weights)
// ---------------------------------------------------------------------------
__global__ void __launch_bounds__(256) cvt_kernel(const float* __restrict__ src,
                                                  __nv_bfloat16* __restrict__ oh,
                                                  __nv_bfloat16* __restrict__ ol,
                                                  int n4) {
    int i = blockIdx.x * blockDim.x + threadIdx.x;
    if (i >= n4) return;
    float4 v = ((const float4*)src)[i];
    size_t base = (size_t)i * 4;
    uint32_t h01, l01, h23, l23;
    split2(v.x, v.y, h01, l01);
    split2(v.z, v.w, h23, l23);
    ((uint32_t*)(oh + base))[0] = h01;
    ((uint32_t*)(oh + base))[1] = h23;
    ((uint32_t*)(ol + base))[0] = l01;
    ((uint32_t*)(ol + base))[1] = l23;
}

// ---------------------------------------------------------------------------
// HMMA bf16x3 GEMM: C = (Ah+Al) @ (Bh+Bl)^T
// R13 pipeline/loads; MMA issue reordered: split-term loop outermost so
// same-accumulator MMAs are 32 issues apart (hides acc RAW latency).
// Per-accumulator accumulation order (hh, hl, lh) unchanged -> bit-identical.
// ---------------------------------------------------------------------------
#define SPAD 40
#define TILE_ELEMS (128 * SPAD)
#define GEMM_SMEM_BYTES (2 * 4 * TILE_ELEMS * 2)
#define NCHUNK (DD / 32)

#define TILEP(s, arr) ((uint16_t(*)[SPAD])(dsm + (size_t)((s) * 4 + (arr)) * TILE_ELEMS))

__global__ void __launch_bounds__(128, 2) gemm3(const __nv_bfloat16* __restrict__ Ah,
                                                const __nv_bfloat16* __restrict__ Al,
                                                const __nv_bfloat16* __restrict__ Bh,
                                                const __nv_bfloat16* __restrict__ Bl,
                                                float* __restrict__ Cf,
                                                __nv_bfloat16* __restrict__ Chi,
                                                __nv_bfloat16* __restrict__ Clo,
                                                int Ntot) {
    extern __shared__ __align__(16) uint16_t dsm[];

    int tid = threadIdx.x;
    int wid = tid >> 5, lid = tid & 31;
    int wm = wid >> 1, wn = wid & 1;
    int g = lid >> 2, t = lid & 3;
    int bm = blockIdx.y * 128;
    int bn = blockIdx.x * 128;

    int a_row  = (lid & 7) + ((lid >> 3) & 1) * 8;
    int a_kcol = (lid >> 4) * 8;
    int b_row  = (lid & 7) + ((lid >> 4) & 1) * 8;
    int b_kcol = ((lid >> 3) & 1) * 8;

    float acc[4][8][4];
    #pragma unroll
    for (int i = 0; i < 4; i++)
        #pragma unroll
        for (int j = 0; j < 8; j++)
            #pragma unroll
            for (int r = 0; r < 4; r++) acc[i][j][r] = 0.f;

    #define GISSUE(s, kc) do { \
        uint16_t (*tAh)[SPAD] = TILEP(s, 0); \
        uint16_t (*tAl)[SPAD] = TILEP(s, 1); \
        uint16_t (*tBh)[SPAD] = TILEP(s, 2); \
        uint16_t (*tBl)[SPAD] = TILEP(s, 3); \
        _Pragma("unroll") \
        for (int c = 0; c < 4; c++) { \
            int idx = tid + c * 128; \
            int row = idx >> 2, c8 = idx & 3; \
            size_t ga = (size_t)(bm + row) * DD + (kc) + c8 * 8; \
            size_t gb = (size_t)(bn + row) * DD + (kc) + c8 * 8; \
            CP16(sptr(&tAh[row][c8 * 8]), Ah + ga); \
            CP16(sptr(&tAl[row][c8 * 8]), Al + ga); \
            CP16(sptr(&tBh[row][c8 * 8]), Bh + gb); \
            CP16(sptr(&tBl[row][c8 * 8]), Bl + gb); \
        } \
        CP_COMMIT(); \
    } while (0)

    GISSUE(0, 0);

    for (int ch = 0; ch < NCHUNK; ch++) {
        int cur = ch & 1;
        if (ch + 1 < NCHUNK) {
            GISSUE((ch + 1) & 1, (ch + 1) * 32);
            asm volatile("cp.async.wait_group 1;" ::: "memory");
        } else {
            asm volatile("cp.async.wait_group 0;" ::: "memory");
        }
        __syncthreads();

        uint16_t (*sAh)[SPAD] = TILEP(cur, 0);
        uint16_t (*sAl)[SPAD] = TILEP(cur, 1);
        uint16_t (*sBh)[SPAD] = TILEP(cur, 2);
        uint16_t (*sBl)[SPAD] = TILEP(cur, 3);

        #pragma unroll
        for (int ks = 0; ks < 2; ks++) {
            int kb = ks * 16;
            uint32_t ah[4][4], al[4][4], bh[8][2], bl[8][2];
            #pragma unroll
            for (int i = 0; i < 4; i++) {
                int m0 = wm * 64 + i * 16;
                LDSM_X4(ah[i], sptr(&sAh[m0 + a_row][kb + a_kcol]));
                LDSM_X4(al[i], sptr(&sAl[m0 + a_row][kb + a_kcol]));
            }
            #pragma unroll
            for (int jp = 0; jp < 4; jp++) {
                int n0 = wn * 64 + jp * 16;
                uint32_t rh[4], rl[4];
                LDSM_X4(rh, sptr(&sBh[n0 + b_row][kb + b_kcol]));
                LDSM_X4(rl, sptr(&sBl[n0 + b_row][kb + b_kcol]));
                bh[2 * jp][0]     = rh[0]; bh[2 * jp][1]     = rh[1];
                bh[2 * jp + 1][0] = rh[2]; bh[2 * jp + 1][1] = rh[3];
                bl[2 * jp][0]     = rl[0]; bl[2 * jp][1]     = rl[1];
                bl[2 * jp + 1][0] = rl[2]; bl[2 * jp + 1][1] = rl[3];
            }
            // ---- pass 1: Ah * Bh
            #pragma unroll
            for (int i = 0; i < 4; i++)
                #pragma unroll
                for (int j = 0; j < 8; j++)
                    MMA16816(acc[i][j], ah[i], bh[j]);
            // ---- pass 2: Ah * Bl
            #pragma unroll
            for (int i = 0; i < 4; i++)
                #pragma unroll
                for (int j = 0; j < 8; j++)
                    MMA16816(acc[i][j], ah[i], bl[j]);
            // ---- pass 3: Al * Bh
            #pragma unroll
            for (int i = 0; i < 4; i++)
                #pragma unroll
                for (int j = 0; j < 8; j++)
                    MMA16816(acc[i][j], al[i], bh[j]);
        }
        __syncthreads();
    }

    if (Cf) {
        #pragma unroll
        for (int i = 0; i < 4; i++) {
            int r0 = bm + wm * 64 + i * 16 + g;
            #pragma unroll
            for (int j = 0; j < 8; j++) {
                int c0 = bn + wn * 64 + j * 8 + 2 * t;
                *(float2*)&Cf[(size_t)r0 * Ntot + c0]       = make_float2(acc[i][j][0], acc[i][j][1]);
                *(float2*)&Cf[(size_t)(r0 + 8) * Ntot + c0] = make_float2(acc[i][j][2], acc[i][j][3]);
            }
        }
    } else {
        #pragma unroll
        for (int i = 0; i < 4; i++) {
            int r0 = bm + wm * 64 + i * 16 + g;
            #pragma unroll
            for (int j = 0; j < 8; j++) {
                int c0 = bn + wn * 64 + j * 8 + 2 * t;
                uint32_t hA, lA, hB, lB;
                split2(acc[i][j][0], acc[i][j][1], hA, lA);
                split2(acc[i][j][2], acc[i][j][3], hB, lB);
                *(uint32_t*)&Chi[(size_t)r0 * Ntot + c0]       = hA;
                *(uint32_t*)&Clo[(size_t)r0 * Ntot + c0]       = lA;
                *(uint32_t*)&Chi[(size_t)(r0 + 8) * Ntot + c0] = hB;
                *(uint32_t*)&Clo[(size_t)(r0 + 8) * Ntot + c0] = lB;
            }
        }
    }
}

// ---------------------------------------------------------------------------
// HMMA flash attention v4 (causal): R12/R13 structure with MMA issue
// reordered into split-term passes (S and PV loops), fragments preloaded.
// Per-accumulator accumulation order unchanged -> bit-identical results.
// ---------------------------------------------------------------------------
#define APAD 72

__global__ void __launch_bounds__(128, 2) attn_hmma() {
    int qt  = gridDim.x - 1 - blockIdx.x;   // heavy tiles first
    int bh  = blockIdx.y;
    int b   = bh >> 4;
    int h   = bh & 15;
    int tid = threadIdx.x;
    int w   = tid >> 5, lid = tid & 31;
    int g   = lid >> 2, t = lid & 3;

    __shared__ __align__(16) uint16_t Kh[64][APAD], Kl[64][APAD];
    __shared__ __align__(16) uint16_t Vh[64][APAD], Vl[64][APAD];   // V row-major [key][d]

    int moff = (lid & 7) + ((lid >> 3) & 1) * 8;

    // ---- Q fragments straight from gmem (invariant across key tiles)
    uint32_t qh[4][4], ql[4][4];
    {
        const __nv_bfloat16* qbh = g_qh + (size_t)(b * TT + qt * 64 + w * 16) * D3 + h * 192;
        const __nv_bfloat16* qbl = g_ql + (size_t)(b * TT + qt * 64 + w * 16) * D3 + h * 192;
        #pragma unroll
        for (int ks = 0; ks < 4; ks++) {
            int kb = ks * 16;
            qh[ks][0] = *(const uint32_t*)(qbh + (size_t)g * D3 + kb + 2 * t);
            qh[ks][1] = *(const uint32_t*)(qbh + (size_t)(8 + g) * D3 + kb + 2 * t);
            qh[ks][2] = *(const uint32_t*)(qbh + (size_t)g * D3 + kb + 8 + 2 * t);
            qh[ks][3] = *(const uint32_t*)(qbh + (size_t)(8 + g) * D3 + kb + 8 + 2 * t);
            ql[ks][0] = *(const uint32_t*)(qbl + (size_t)g * D3 + kb + 2 * t);
            ql[ks][1] = *(const uint32_t*)(qbl + (size_t)(8 + g) * D3 + kb + 2 * t);
            ql[ks][2] = *(const uint32_t*)(qbl + (size_t)g * D3 + kb + 8 + 2 * t);
            ql[ks][3] = *(const uint32_t*)(qbl + (size_t)(8 + g) * D3 + kb + 8 + 2 * t);
        }
    }

    float oacc[8][4];
    #pragma unroll
    for (int c = 0; c < 8; c++)
        #pragma unroll
        for (int r = 0; r < 4; r++) oacc[c][r] = 0.f;
    float m0 = -1e30f, m1 = -1e30f, l0 = 0.f, l1 = 0.f;

    int ntiles = qt + 1;
    for (int kt = 0; kt < ntiles; kt++) {
        __syncthreads();
        {
            int r = tid >> 1, half = tid & 1;
            size_t base = (size_t)(b * TT + kt * 64 + r) * D3 + h * 192;
            const uint4* kh4 = (const uint4*)(g_qh + base + 64 + half * 32);
            const uint4* kl4 = (const uint4*)(g_ql + base + 64 + half * 32);
            const uint4* vh4 = (const uint4*)(g_qh + base + 128 + half * 32);
            const uint4* vl4 = (const uint4*)(g_ql + base + 128 + half * 32);
            #pragma unroll
            for (int j = 0; j < 4; j++) {
                *(uint4*)&Kh[r][half * 32 + j * 8] = kh4[j];
                *(uint4*)&Kl[r][half * 32 + j * 8] = kl4[j];
                *(uint4*)&Vh[r][half * 32 + j * 8] = vh4[j];
                *(uint4*)&Vl[r][half * 32 + j * 8] = vl4[j];
            }
        }
        __syncthreads();

        float sf[8][4];
        #pragma unroll
        for (int c = 0; c < 8; c++)
            #pragma unroll
            for (int r = 0; r < 4; r++) sf[c][r] = 0.f;

        #pragma unroll
        for (int ks = 0; ks < 4; ks++) {
            int kb = ks * 16;
            uint32_t bhf[8][2], blf[8][2];
            #pragma unroll
            for (int c = 0; c < 8; c++) {
                bhf[c][0] = *(const uint32_t*)&Kh[c * 8 + g][kb + 2 * t];
                bhf[c][1] = *(const uint32_t*)&Kh[c * 8 + g][kb + 8 + 2 * t];
                blf[c][0] = *(const uint32_t*)&Kl[c * 8 + g][kb + 2 * t];
                blf[c][1] = *(const uint32_t*)&Kl[c * 8 + g][kb + 8 + 2 * t];
            }
            #pragma unroll
            for (int c = 0; c < 8; c++) MMA16816(sf[c], qh[ks], bhf[c]);
            #pragma unroll
            for (int c = 0; c < 8; c++) MMA16816(sf[c], qh[ks], blf[c]);
            #pragma unroll
            for (int c = 0; c < 8; c++) MMA16816(sf[c], ql[ks], bhf[c]);
        }

        #pragma unroll
        for (int c = 0; c < 8; c++) {
            sf[c][0] *= 0.125f; sf[c][1] *= 0.125f;
            sf[c][2] *= 0.125f; sf[c][3] *= 0.125f;
        }

        if (kt == qt) {
            int colb = kt * 64 + 2 * t;
            int row0 = qt * 64 + w * 16 + g;
            #pragma unroll
            for (int c = 0; c < 8; c++) {
                int col = colb + c * 8;
                if (col     > row0)     sf[c][0] = -1e30f;
                if (col + 1 > row0)     sf[c][1] = -1e30f;
                if (col     > row0 + 8) sf[c][2] = -1e30f;
                if (col + 1 > row0 + 8) sf[c][3] = -1e30f;
            }
        }

        float rm0 = -1e30f, rm1 = -1e30f;
        #pragma unroll
        for (int c = 0; c < 8; c++) {
            rm0 = fmaxf(rm0, fmaxf(sf[c][0], sf[c][1]));
            rm1 = fmaxf(rm1, fmaxf(sf[c][2], sf[c][3]));
        }
        rm0 = fmaxf(rm0, __shfl_xor_sync(0xffffffffu, rm0, 1));
        rm0 = fmaxf(rm0, __shfl_xor_sync(0xffffffffu, rm0, 2));
        rm1 = fmaxf(rm1, __shfl_xor_sync(0xffffffffu, rm1, 1));
        rm1 = fmaxf(rm1, __shfl_xor_sync(0xffffffffu, rm1, 2));

        float mn0 = fmaxf(m0, rm0), mn1 = fmaxf(m1, rm1);
        float corr0 = __expf(m0 - mn0), corr1 = __expf(m1 - mn1);
        l0 *= corr0; l1 *= corr1;
        #pragma unroll
        for (int c = 0; c < 8; c++) {
            oacc[c][0] *= corr0; oacc[c][1] *= corr0;
            oacc[c][2] *= corr1; oacc[c][3] *= corr1;
        }

        uint32_t phA[8], phB[8], plA[8], plB[8];
        float rs0 = 0.f, rs1 = 0.f;
        #pragma unroll
        for (int c = 0; c < 8; c++) {
            float p0 = __expf(sf[c][0] - mn0);
            float p1 = __expf(sf[c][1] - mn0);
            float p2 = __expf(sf[c][2] - mn1);
            float p3 = __expf(sf[c][3] - mn1);
            rs0 += p0 + p1; rs1 += p2 + p3;
            split2(p0, p1, phA[c], plA[c]);
            split2(p2, p3, phB[c], plB[c]);
        }
        rs0 += __shfl_xor_sync(0xffffffffu, rs0, 1);
        rs0 += __shfl_xor_sync(0xffffffffu, rs0, 2);
        rs1 += __shfl_xor_sync(0xffffffffu, rs1, 1);
        rs1 += __shfl_xor_sync(0xffffffffu, rs1, 2);
        l0 += rs0; l1 += rs1;
        m0 = mn0; m1 = mn1;

        // ---- P · V: split-term passes per j-step; V fragments preloaded
        #pragma unroll
        for (int j = 0; j < 4; j++) {
            uint32_t a_h[4] = {phA[2 * j], phB[2 * j], phA[2 * j + 1], phB[2 * j + 1]};
            uint32_t a_l[4] = {plA[2 * j], plB[2 * j], plA[2 * j + 1], plB[2 * j + 1]};
            int kb = j * 16;
            uint32_t vh[8][2], vl[8][2];
            #pragma unroll
            for (int c = 0; c < 8; c++) {
                LDSMT_X2(vh[c], sptr(&Vh[kb + moff][c * 8]));
                LDSMT_X2(vl[c], sptr(&Vl[kb + moff][c * 8]));
            }
            #pragma unroll
            for (int c = 0; c < 8; c++) MMA16816(oacc[c], a_h, vh[c]);
            #pragma unroll
            for (int c = 0; c < 8; c++) MMA16816(oacc[c], a_h, vl[c]);
            #pragma unroll
            for (int c = 0; c < 8; c++) MMA16816(oacc[c], a_l, vh[c]);
        }
    }

    float il0 = 1.f / l0, il1 = 1.f / l1;
    int row0 = b * TT + qt * 64 + w * 16 + g;
    #pragma unroll
    for (int c = 0; c < 8; c++) {
        int col = h * DHD + c * 8 + 2 * t;
        uint32_t hA, lA, hB, lB;
        split2(oacc[c][0] * il0, oacc[c][1] * il0, hA, lA);
        split2(oacc[c][2] * il1, oacc[c][3] * il1, hB, lB);
        *(uint32_t*)&g_cxh[(size_t)row0 * DD + col]       = hA;
        *(uint32_t*)&g_cxl[(size_t)row0 * DD + col]       = lA;
        *(uint32_t*)&g_cxh[(size_t)(row0 + 8) * DD + col] = hB;
        *(uint32_t*)&g_cxl[(size_t)(row0 + 8) * DD + col] = lB;
    }
}

// ---------------------------------------------------------------------------
// Launch
// ---------------------------------------------------------------------------
extern "C" void kernel_launch(void* const* d_in, const int* in_sizes, int n_in,
                              void* d_out, int out_size) {
    const float* x     = (const float*)d_in[0];
    const float* gamma = (const float*)d_in[1];
    const float* beta  = (const float*)d_in[2];
    const float* w_qkv = (const float*)d_in[3];   // [3072, 1024]
    const float* w_o   = (const float*)d_in[4];   // [1024, 1024]
    float* out = (float*)d_out;                   // [8192, 1024]

    __nv_bfloat16 *qh, *ql, *xnh, *xnl, *wqh, *wql, *woh, *wol, *cxh, *cxl;
    cudaGetSymbolAddress((void**)&qh,  g_qh);
    cudaGetSymbolAddress((void**)&ql,  g_ql);
    cudaGetSymbolAddress((void**)&xnh, g_xnh);
    cudaGetSymbolAddress((void**)&xnl, g_xnl);
    cudaGetSymbolAddress((void**)&wqh, g_wqh);
    cudaGetSymbolAddress((void**)&wql, g_wql);
    cudaGetSymbolAddress((void**)&woh, g_woh);
    cudaGetSymbolAddress((void**)&wol, g_wol);
    cudaGetSymbolAddress((void**)&cxh, g_cxh);
    cudaGetSymbolAddress((void**)&cxl, g_cxl);

    static int attr_set = 0;
    if (!attr_set) {
        cudaFuncSetAttribute(gemm3, cudaFuncAttributeMaxDynamicSharedMemorySize,
                             GEMM_SMEM_BYTES);
        attr_set = 1;
    }

    // 1. LayerNorm (fused bf16 hi/lo split output)
    ln_kernel<<<BT, 256>>>(x, gamma, beta);

    // 2. Weight splits
    cvt_kernel<<<(D3 * DD / 4 + 255) / 256, 256>>>(w_qkv, wqh, wql, D3 * DD / 4);
    cvt_kernel<<<(DD * DD / 4 + 255) / 256, 256>>>(w_o, woh, wol, DD * DD / 4);

    // 3. QKV projection -> bf16 hi/lo output
    {
        dim3 grid(D3 / 128, BT / 128);
        gemm3<<<grid, 128, GEMM_SMEM_BYTES>>>(xnh, xnl, wqh, wql, nullptr, qh, ql, D3);
    }

    // 4. Causal attention (HMMA flash v4)
    {
        dim3 grid(TT / 64, NB * HH);
        attn_hmma<<<grid, 128>>>();
    }

    // 5. Output projection (fp32 out)
    {
        dim3 grid(DD / 128, BT / 128);
        gemm3<<<grid, 128, GEMM_SMEM_BYTES>>>(cxh, cxl, woh, wol, out, nullptr, nullptr, DD);
    }
}

// round 15
// speedup vs baseline: 1.5233x; 1.5233x over previous
#include <cuda_runtime.h>
#include <cuda_bf16.h>
#include <math.h>
#include <stdint.h>

// Problem constants
#define NB   4
#define TT   2048
#define DD   1024
#define HH   16
#define DHD  64
#define BT   (NB * TT)          // 8192 rows
#define D3   (3 * DD)           // 3072

// ---------------------------------------------------------------------------
// Scratch (no cudaMalloc allowed — device globals)
// ---------------------------------------------------------------------------
__device__ __nv_bfloat16 g_qh[BT * D3], g_ql[BT * D3];     // QKV bf16 hi/lo
__device__ __nv_bfloat16 g_xnh[BT * DD], g_xnl[BT * DD];   // LN output hi/lo
__device__ __nv_bfloat16 g_wqh[D3 * DD], g_wql[D3 * DD];   // W_qkv hi/lo
__device__ __nv_bfloat16 g_woh[DD * DD], g_wol[DD * DD];   // W_o hi/lo
__device__ __nv_bfloat16 g_cxh[BT * DD], g_cxl[BT * DD];   // ctx hi/lo (attn out)

// ---------------------------------------------------------------------------
// PTX helpers
// ---------------------------------------------------------------------------
#define MMA16816(Cacc, Afrag, Bfrag) \
    asm volatile( \
        "mma.sync.aligned.m16n8k16.row.col.f32.bf16.bf16.f32 " \
        "{%0,%1,%2,%3}, {%4,%5,%6,%7}, {%8,%9}, {%0,%1,%2,%3};" \
        : "+f"((Cacc)[0]), "+f"((Cacc)[1]), "+f"((Cacc)[2]), "+f"((Cacc)[3]) \
        : "r"((Afrag)[0]), "r"((Afrag)[1]), "r"((Afrag)[2]), "r"((Afrag)[3]), \
          "r"((Bfrag)[0]), "r"((Bfrag)[1]))

#define CP16(saddr, gptr) \
    asm volatile("cp.async.cg.shared.global [%0], [%1], 16;" :: "r"(saddr), "l"(gptr))
#define CP_COMMIT() asm volatile("cp.async.commit_group;" ::: "memory")

#define LDSM_X4(r, a) \
    asm volatile("ldmatrix.sync.aligned.m8n8.x4.shared.b16 {%0,%1,%2,%3}, [%4];" \
                 : "=r"((r)[0]), "=r"((r)[1]), "=r"((r)[2]), "=r"((r)[3]) : "r"(a))

#define LDSMT_X2(r, a) \
    asm volatile("ldmatrix.sync.aligned.m8n8.x2.trans.shared.b16 {%0,%1}, [%2];" \
                 : "=r"((r)[0]), "=r"((r)[1]) : "r"(a))

__device__ __forceinline__ uint32_t sptr(const void* p) {
    return (uint32_t)__cvta_generic_to_shared(p);
}

__device__ __forceinline__ void split2(float a, float b, uint32_t& hi, uint32_t& lo) {
    __nv_bfloat16 ha = __float2bfloat16(a), hb = __float2bfloat16(b);
    __nv_bfloat16 la = __float2bfloat16(a - __bfloat162float(ha));
    __nv_bfloat16 lb = __float2bfloat16(b - __bfloat162float(hb));
    __nv_bfloat162 th = __halves2bfloat162(ha, hb);
    __nv_bfloat162 tl = __halves2bfloat162(la, lb);
    hi = *reinterpret_cast<uint32_t*>(&th);
    lo = *reinterpret_cast<uint32_t*>(&tl);
}

// ---------------------------------------------------------------------------
// LayerNorm: one block (256 threads) per row; writes bf16 hi/lo split
// ---------------------------------------------------------------------------
__global__ void __launch_bounds__(256) ln_kernel(const float* __restrict__ x,
                                                 const float* __restrict__ gamma,
                                                 const float* __restrict__ beta) {
    int row = blockIdx.x;
    int tid = threadIdx.x;
    __shared__ float red[2][8];

    const float4* xr = (const float4*)(x + (size_t)row * DD);
    float4 xv = xr[tid];
    float s  = xv.x + xv.y + xv.z + xv.w;
    float s2 = xv.x * xv.x + xv.y * xv.y + xv.z * xv.z + xv.w * xv.w;

    #pragma unroll
    for (int o = 16; o > 0; o >>= 1) {
        s  += __shfl_xor_sync(0xffffffffu, s, o);
        s2 += __shfl_xor_sync(0xffffffffu, s2, o);
    }
    if ((tid & 31) == 0) { red[0][tid >> 5] = s; red[1][tid >> 5] = s2; }
    __syncthreads();
    if (tid < 32) {
        float a = (tid < 8) ? red[0][tid] : 0.f;
        float b = (tid < 8) ? red[1][tid] : 0.f;
        #pragma unroll
        for (int o = 4; o > 0; o >>= 1) {
            a += __shfl_xor_sync(0xffffffffu, a, o);
            b += __shfl_xor_sync(0xffffffffu, b, o);
        }
        if (tid == 0) { red[0][0] = a * (1.f / DD); red[1][0] = b * (1.f / DD); }
    }
    __syncthreads();

    float mu   = red[0][0];
    float var  = red[1][0] - mu * mu;
    float rstd = rsqrtf(var + 1e-5f);

    float4 g  = ((const float4*)gamma)[tid];
    float4 bb = ((const float4*)beta)[tid];
    float y[4];
    y[0] = (xv.x - mu) * rstd * g.x + bb.x;
    y[1] = (xv.y - mu) * rstd * g.y + bb.y;
    y[2] = (xv.z - mu) * rstd * g.z + bb.z;
    y[3] = (xv.w - mu) * rstd * g.w + bb.w;

    size_t base = (size_t)row * DD + tid * 4;
    uint32_t h01, l01, h23, l23;
    split2(y[0], y[1], h01, l01);
    split2(y[2], y[3], h23, l23);
    ((uint32_t*)(g_xnh + base))[0] = h01;
    ((uint32_t*)(g_xnh + base))[1] = h23;
    ((uint32_t*)(g_xnl + base))[0] = l01;
    ((uint32_t*)(g_xnl + base))[1] = l23;
}

// ---------------------------------------------------------------------------
// fp32 -> bf16 hi/lo split convert (weights)
// ---------------------------------------------------------------------------
__global__ void __launch_bounds__(256) cvt_kernel(const float* __restrict__ src,
                                                  __nv_bfloat16* __restrict__ oh,
                                                  __nv_bfloat16* __restrict__ ol,
                                                  int n4) {
    int i = blockIdx.x * blockDim.x + threadIdx.x;
    if (i >= n4) return;
    float4 v = ((const float4*)src)[i];
    size_t base = (size_t)i * 4;
    uint32_t h01, l01, h23, l23;
    split2(v.x, v.y, h01, l01);
    split2(v.z, v.w, h23, l23);
    ((uint32_t*)(oh + base))[0] = h01;
    ((uint32_t*)(oh + base))[1] = h23;
    ((uint32_t*)(ol + base))[0] = l01;
    ((uint32_t*)(ol + base))[1] = l23;
}

// ---------------------------------------------------------------------------
// HMMA bf16x3 GEMM (VERBATIM from R13 pass): C = (Ah+Al) @ (Bh+Bl)^T
// cp.async pipeline + ldmatrix loads, interleaved MMA order (hh,hl,lh per ij).
// ---------------------------------------------------------------------------
#define SPAD 40
#define TILE_ELEMS (128 * SPAD)
#define GEMM_SMEM_BYTES (2 * 4 * TILE_ELEMS * 2)
#define NCHUNK (DD / 32)

#define TILEP(s, arr) ((uint16_t(*)[SPAD])(dsm + (size_t)((s) * 4 + (arr)) * TILE_ELEMS))

__global__ void __launch_bounds__(128, 2) gemm3(const __nv_bfloat16* __restrict__ Ah,
                                                const __nv_bfloat16* __restrict__ Al,
                                                const __nv_bfloat16* __restrict__ Bh,
                                                const __nv_bfloat16* __restrict__ Bl,
                                                float* __restrict__ Cf,
                                                __nv_bfloat16* __restrict__ Chi,
                                                __nv_bfloat16* __restrict__ Clo,
                                                int Ntot) {
    extern __shared__ __align__(16) uint16_t dsm[];

    int tid = threadIdx.x;
    int wid = tid >> 5, lid = tid & 31;
    int wm = wid >> 1, wn = wid & 1;
    int g = lid >> 2, t = lid & 3;
    int bm = blockIdx.y * 128;
    int bn = blockIdx.x * 128;

    int a_row  = (lid & 7) + ((lid >> 3) & 1) * 8;
    int a_kcol = (lid >> 4) * 8;
    int b_row  = (lid & 7) + ((lid >> 4) & 1) * 8;
    int b_kcol = ((lid >> 3) & 1) * 8;

    float acc[4][8][4];
    #pragma unroll
    for (int i = 0; i < 4; i++)
        #pragma unroll
        for (int j = 0; j < 8; j++)
            #pragma unroll
            for (int r = 0; r < 4; r++) acc[i][j][r] = 0.f;

    #define GISSUE(s, kc) do { \
        uint16_t (*tAh)[SPAD] = TILEP(s, 0); \
        uint16_t (*tAl)[SPAD] = TILEP(s, 1); \
        uint16_t (*tBh)[SPAD] = TILEP(s, 2); \
        uint16_t (*tBl)[SPAD] = TILEP(s, 3); \
        _Pragma("unroll") \
        for (int c = 0; c < 4; c++) { \
            int idx = tid + c * 128; \
            int row = idx >> 2, c8 = idx & 3; \
            size_t ga = (size_t)(bm + row) * DD + (kc) + c8 * 8; \
            size_t gb = (size_t)(bn + row) * DD + (kc) + c8 * 8; \
            CP16(sptr(&tAh[row][c8 * 8]), Ah + ga); \
            CP16(sptr(&tAl[row][c8 * 8]), Al + ga); \
            CP16(sptr(&tBh[row][c8 * 8]), Bh + gb); \
            CP16(sptr(&tBl[row][c8 * 8]), Bl + gb); \
        } \
        CP_COMMIT(); \
    } while (0)

    GISSUE(0, 0);

    for (int ch = 0; ch < NCHUNK; ch++) {
        int cur = ch & 1;
        if (ch + 1 < NCHUNK) {
            GISSUE((ch + 1) & 1, (ch + 1) * 32);
            asm volatile("cp.async.wait_group 1;" ::: "memory");
        } else {
            asm volatile("cp.async.wait_group 0;" ::: "memory");
        }
        __syncthreads();

        uint16_t (*sAh)[SPAD] = TILEP(cur, 0);
        uint16_t (*sAl)[SPAD] = TILEP(cur, 1);
        uint16_t (*sBh)[SPAD] = TILEP(cur, 2);
        uint16_t (*sBl)[SPAD] = TILEP(cur, 3);

        #pragma unroll
        for (int ks = 0; ks < 2; ks++) {
            int kb = ks * 16;
            uint32_t ah[4][4], al[4][4], bh[8][2], bl[8][2];
            #pragma unroll
            for (int i = 0; i < 4; i++) {
                int m0 = wm * 64 + i * 16;
                LDSM_X4(ah[i], sptr(&sAh[m0 + a_row][kb + a_kcol]));
                LDSM_X4(al[i], sptr(&sAl[m0 + a_row][kb + a_kcol]));
            }
            #pragma unroll
            for (int jp = 0; jp < 4; jp++) {
                int n0 = wn * 64 + jp * 16;
                uint32_t rh[4], rl[4];
                LDSM_X4(rh, sptr(&sBh[n0 + b_row][kb + b_kcol]));
                LDSM_X4(rl, sptr(&sBl[n0 + b_row][kb + b_kcol]));
                bh[2 * jp][0]     = rh[0]; bh[2 * jp][1]     = rh[1];
                bh[2 * jp + 1][0] = rh[2]; bh[2 * jp + 1][1] = rh[3];
                bl[2 * jp][0]     = rl[0]; bl[2 * jp][1]     = rl[1];
                bl[2 * jp + 1][0] = rl[2]; bl[2 * jp + 1][1] = rl[3];
            }
            #pragma unroll
            for (int i = 0; i < 4; i++)
                #pragma unroll
                for (int j = 0; j < 8; j++) {
                    MMA16816(acc[i][j], ah[i], bh[j]);
                    MMA16816(acc[i][j], ah[i], bl[j]);
                    MMA16816(acc[i][j], al[i], bh[j]);
                }
        }
        __syncthreads();
    }

    if (Cf) {
        #pragma unroll
        for (int i = 0; i < 4; i++) {
            int r0 = bm + wm * 64 + i * 16 + g;
            #pragma unroll
            for (int j = 0; j < 8; j++) {
                int c0 = bn + wn * 64 + j * 8 + 2 * t;
                *(float2*)&Cf[(size_t)r0 * Ntot + c0]       = make_float2(acc[i][j][0], acc[i][j][1]);
                *(float2*)&Cf[(size_t)(r0 + 8) * Ntot + c0] = make_float2(acc[i][j][2], acc[i][j][3]);
            }
        }
    } else {
        #pragma unroll
        for (int i = 0; i < 4; i++) {
            int r0 = bm + wm * 64 + i * 16 + g;
            #pragma unroll
            for (int j = 0; j < 8; j++) {
                int c0 = bn + wn * 64 + j * 8 + 2 * t;
                uint32_t hA, lA, hB, lB;
                split2(acc[i][j][0], acc[i][j][1], hA, lA);
                split2(acc[i][j][2], acc[i][j][3], hB, lB);
                *(uint32_t*)&Chi[(size_t)r0 * Ntot + c0]       = hA;
                *(uint32_t*)&Clo[(size_t)r0 * Ntot + c0]       = lA;
                *(uint32_t*)&Chi[(size_t)(r0 + 8) * Ntot + c0] = hB;
                *(uint32_t*)&Clo[(size_t)(r0 + 8) * Ntot + c0] = lB;
            }
        }
    }
}

// ---------------------------------------------------------------------------
// HMMA flash attention v5 (causal), bf16x3 splits.
// R13 compute body (interleaved MMA order) + 2-stage cp.async double-buffered
// K/V staging (dynamic smem ring, gemm3's proven protocol).
// 128 threads (4 warps x 16 q-rows), key tiles of 64, 2 CTAs/SM.
// ---------------------------------------------------------------------------
#define APAD 72
#define ATILE (64 * APAD)                       // elems per array
#define ATTN_SMEM_BYTES (2 * 4 * ATILE * 2)     // 2 stages x (Kh,Kl,Vh,Vl) = 73728 B

#define ATILEP(s, arr) ((uint16_t(*)[APAD])(asm_ + (size_t)((s) * 4 + (arr)) * ATILE))

__global__ void __launch_bounds__(128, 2) attn_hmma() {
    extern __shared__ __align__(16) uint16_t asm_[];

    int qt  = gridDim.x - 1 - blockIdx.x;   // heavy tiles first
    int bh  = blockIdx.y;
    int b   = bh >> 4;
    int h   = bh & 15;
    int tid = threadIdx.x;
    int w   = tid >> 5, lid = tid & 31;
    int g   = lid >> 2, t = lid & 3;

    int moff = (lid & 7) + ((lid >> 3) & 1) * 8;
    int srow = tid >> 1, shalf = tid & 1;      // staging row / half

    // ---- Q fragments straight from gmem (invariant across key tiles)
    uint32_t qh[4][4], ql[4][4];
    {
        const __nv_bfloat16* qbh = g_qh + (size_t)(b * TT + qt * 64 + w * 16) * D3 + h * 192;
        const __nv_bfloat16* qbl = g_ql + (size_t)(b * TT + qt * 64 + w * 16) * D3 + h * 192;
        #pragma unroll
        for (int ks = 0; ks < 4; ks++) {
            int kb = ks * 16;
            qh[ks][0] = *(const uint32_t*)(qbh + (size_t)g * D3 + kb + 2 * t);
            qh[ks][1] = *(const uint32_t*)(qbh + (size_t)(8 + g) * D3 + kb + 2 * t);
            qh[ks][2] = *(const uint32_t*)(qbh + (size_t)g * D3 + kb + 8 + 2 * t);
            qh[ks][3] = *(const uint32_t*)(qbh + (size_t)(8 + g) * D3 + kb + 8 + 2 * t);
            ql[ks][0] = *(const uint32_t*)(qbl + (size_t)g * D3 + kb + 2 * t);
            ql[ks][1] = *(const uint32_t*)(qbl + (size_t)(8 + g) * D3 + kb + 2 * t);
            ql[ks][2] = *(const uint32_t*)(qbl + (size_t)g * D3 + kb + 8 + 2 * t);
            ql[ks][3] = *(const uint32_t*)(qbl + (size_t)(8 + g) * D3 + kb + 8 + 2 * t);
        }
    }

    // ---- stage issue macro: K/V tile kt -> ring stage s (pure cp.async)
    #define AISSUE(s, kt) do { \
        uint16_t (*tKh)[APAD] = ATILEP(s, 0); \
        uint16_t (*tKl)[APAD] = ATILEP(s, 1); \
        uint16_t (*tVh)[APAD] = ATILEP(s, 2); \
        uint16_t (*tVl)[APAD] = ATILEP(s, 3); \
        size_t base = (size_t)(b * TT + (kt) * 64 + srow) * D3 + h * 192; \
        const __nv_bfloat16* kh = g_qh + base + 64 + shalf * 32; \
        const __nv_bfloat16* kl = g_ql + base + 64 + shalf * 32; \
        const __nv_bfloat16* vh = g_qh + base + 128 + shalf * 32; \
        const __nv_bfloat16* vl = g_ql + base + 128 + shalf * 32; \
        _Pragma("unroll") \
        for (int j = 0; j < 4; j++) { \
            CP16(sptr(&tKh[srow][shalf * 32 + j * 8]), kh + j * 8); \
            CP16(sptr(&tKl[srow][shalf * 32 + j * 8]), kl + j * 8); \
            CP16(sptr(&tVh[srow][shalf * 32 + j * 8]), vh + j * 8); \
            CP16(sptr(&tVl[srow][shalf * 32 + j * 8]), vl + j * 8); \
        } \
        CP_COMMIT(); \
    } while (0)

    float oacc[8][4];
    #pragma unroll
    for (int c = 0; c < 8; c++)
        #pragma unroll
        for (int r = 0; r < 4; r++) oacc[c][r] = 0.f;
    float m0 = -1e30f, m1 = -1e30f, l0 = 0.f, l1 = 0.f;

    int ntiles = qt + 1;
    AISSUE(0, 0);

    for (int kt = 0; kt < ntiles; kt++) {
        int cur = kt & 1;
        if (kt + 1 < ntiles) {
            AISSUE((kt + 1) & 1, kt + 1);
            asm volatile("cp.async.wait_group 1;" ::: "memory");
        } else {
            asm volatile("cp.async.wait_group 0;" ::: "memory");
        }
        __syncthreads();

        uint16_t (*Kh)[APAD] = ATILEP(cur, 0);
        uint16_t (*Kl)[APAD] = ATILEP(cur, 1);
        uint16_t (*Vh)[APAD] = ATILEP(cur, 2);
        uint16_t (*Vl)[APAD] = ATILEP(cur, 3);

        // ---- S = Q K^T (3-term), fragment accumulators
        float sf[8][4];
        #pragma unroll
        for (int c = 0; c < 8; c++)
            #pragma unroll
            for (int r = 0; r < 4; r++) sf[c][r] = 0.f;

        #pragma unroll
        for (int ks = 0; ks < 4; ks++) {
            int kb = ks * 16;
            #pragma unroll
            for (int c = 0; c < 8; c++) {
                uint32_t bhf[2], blf[2];
                bhf[0] = *(const uint32_t*)&Kh[c * 8 + g][kb + 2 * t];
                bhf[1] = *(const uint32_t*)&Kh[c * 8 + g][kb + 8 + 2 * t];
                blf[0] = *(const uint32_t*)&Kl[c * 8 + g][kb + 2 * t];
                blf[1] = *(const uint32_t*)&Kl[c * 8 + g][kb + 8 + 2 * t];
                MMA16816(sf[c], qh[ks], bhf);
                MMA16816(sf[c], qh[ks], blf);
                MMA16816(sf[c], ql[ks], bhf);
            }
        }

        #pragma unroll
        for (int c = 0; c < 8; c++) {
            sf[c][0] *= 0.125f; sf[c][1] *= 0.125f;
            sf[c][2] *= 0.125f; sf[c][3] *= 0.125f;
        }

        // ---- causal mask (only the diagonal tile)
        if (kt == qt) {
            int colb = kt * 64 + 2 * t;
            int row0 = qt * 64 + w * 16 + g;
            #pragma unroll
            for (int c = 0; c < 8; c++) {
                int col = colb + c * 8;
                if (col     > row0)     sf[c][0] = -1e30f;
                if (col + 1 > row0)     sf[c][1] = -1e30f;
                if (col     > row0 + 8) sf[c][2] = -1e30f;
                if (col + 1 > row0 + 8) sf[c][3] = -1e30f;
            }
        }

        // ---- online softmax on fragments
        float rm0 = -1e30f, rm1 = -1e30f;
        #pragma unroll
        for (int c = 0; c < 8; c++) {
            rm0 = fmaxf(rm0, fmaxf(sf[c][0], sf[c][1]));
            rm1 = fmaxf(rm1, fmaxf(sf[c][2], sf[c][3]));
        }
        rm0 = fmaxf(rm0, __shfl_xor_sync(0xffffffffu, rm0, 1));
        rm0 = fmaxf(rm0, __shfl_xor_sync(0xffffffffu, rm0, 2));
        rm1 = fmaxf(rm1, __shfl_xor_sync(0xffffffffu, rm1, 1));
        rm1 = fmaxf(rm1, __shfl_xor_sync(0xffffffffu, rm1, 2));

        float mn0 = fmaxf(m0, rm0), mn1 = fmaxf(m1, rm1);
        float corr0 = __expf(m0 - mn0), corr1 = __expf(m1 - mn1);
        l0 *= corr0; l1 *= corr1;
        #pragma unroll
        for (int c = 0; c < 8; c++) {
            oacc[c][0] *= corr0; oacc[c][1] *= corr0;
            oacc[c][2] *= corr1; oacc[c][3] *= corr1;
        }

        uint32_t phA[8], phB[8], plA[8], plB[8];
        float rs0 = 0.f, rs1 = 0.f;
        #pragma unroll
        for (int c = 0; c < 8; c++) {
            float p0 = __expf(sf[c][0] - mn0);
            float p1 = __expf(sf[c][1] - mn0);
            float p2 = __expf(sf[c][2] - mn1);
            float p3 = __expf(sf[c][3] - mn1);
            rs0 += p0 + p1; rs1 += p2 + p3;
            split2(p0, p1, phA[c], plA[c]);
            split2(p2, p3, phB[c], plB[c]);
        }
        rs0 += __shfl_xor_sync(0xffffffffu, rs0, 1);
        rs0 += __shfl_xor_sync(0xffffffffu, rs0, 2);
        rs1 += __shfl_xor_sync(0xffffffffu, rs1, 1);
        rs1 += __shfl_xor_sync(0xffffffffu, rs1, 2);
        l0 += rs0; l1 += rs1;
        m0 = mn0; m1 = mn1;

        // ---- P · V (3-term): B fragments via ldmatrix.x2.trans on V[key][d]
        #pragma unroll
        for (int j = 0; j < 4; j++) {
            uint32_t a_h[4] = {phA[2 * j], phB[2 * j], phA[2 * j + 1], phB[2 * j + 1]};
            uint32_t a_l[4] = {plA[2 * j], plB[2 * j], plA[2 * j + 1], plB[2 * j + 1]};
            int kb = j * 16;
            #pragma unroll
            for (int c = 0; c < 8; c++) {
                uint32_t vh[2], vl[2];
                LDSMT_X2(vh, sptr(&Vh[kb + moff][c * 8]));
                LDSMT_X2(vl, sptr(&Vl[kb + moff][c * 8]));
                MMA16816(oacc[c], a_h, vh);
                MMA16816(oacc[c], a_h, vl);
                MMA16816(oacc[c], a_l, vh);
            }
        }
        __syncthreads();   // guard: next AISSUE must not overwrite a stage in use
    }

    // ---- epilogue: divide by l, hi/lo split, write to g_cxh/g_cxl
    float il0 = 1.f / l0, il1 = 1.f / l1;
    int row0 = b * TT + qt * 64 + w * 16 + g;
    #pragma unroll
    for (int c = 0; c < 8; c++) {
        int col = h * DHD + c * 8 + 2 * t;
        uint32_t hA, lA, hB, lB;
        split2(oacc[c][0] * il0, oacc[c][1] * il0, hA, lA);
        split2(oacc[c][2] * il1, oacc[c][3] * il1, hB, lB);
        *(uint32_t*)&g_cxh[(size_t)row0 * DD + col]       = hA;
        *(uint32_t*)&g_cxl[(size_t)row0 * DD + col]       = lA;
        *(uint32_t*)&g_cxh[(size_t)(row0 + 8) * DD + col] = hB;
        *(uint32_t*)&g_cxl[(size_t)(row0 + 8) * DD + col] = lB;
    }
}

// ---------------------------------------------------------------------------
// Launch
// ---------------------------------------------------------------------------
extern "C" void kernel_launch(void* const* d_in, const int* in_sizes, int n_in,
                              void* d_out, int out_size) {
    const float* x     = (const float*)d_in[0];
    const float* gamma = (const float*)d_in[1];
    const float* beta  = (const float*)d_in[2];
    const float* w_qkv = (const float*)d_in[3];   // [3072, 1024]
    const float* w_o   = (const float*)d_in[4];   // [1024, 1024]
    float* out = (float*)d_out;                   // [8192, 1024]

    __nv_bfloat16 *qh, *ql, *xnh, *xnl, *wqh, *wql, *woh, *wol, *cxh, *cxl;
    cudaGetSymbolAddress((void**)&qh,  g_qh);
    cudaGetSymbolAddress((void**)&ql,  g_ql);
    cudaGetSymbolAddress((void**)&xnh, g_xnh);
    cudaGetSymbolAddress((void**)&xnl, g_xnl);
    cudaGetSymbolAddress((void**)&wqh, g_wqh);
    cudaGetSymbolAddress((void**)&wql, g_wql);
    cudaGetSymbolAddress((void**)&woh, g_woh);
    cudaGetSymbolAddress((void**)&wol, g_wol);
    cudaGetSymbolAddress((void**)&cxh, g_cxh);
    cudaGetSymbolAddress((void**)&cxl, g_cxl);

    static int attr_set = 0;
    if (!attr_set) {
        cudaFuncSetAttribute(gemm3, cudaFuncAttributeMaxDynamicSharedMemorySize,
                             GEMM_SMEM_BYTES);
        cudaFuncSetAttribute(attn_hmma, cudaFuncAttributeMaxDynamicSharedMemorySize,
                             ATTN_SMEM_BYTES);
        attr_set = 1;
    }

    // 1. LayerNorm (fused bf16 hi/lo split output)
    ln_kernel<<<BT, 256>>>(x, gamma, beta);

    // 2. Weight splits
    cvt_kernel<<<(D3 * DD / 4 + 255) / 256, 256>>>(w_qkv, wqh, wql, D3 * DD / 4);
    cvt_kernel<<<(DD * DD / 4 + 255) / 256, 256>>>(w_o, woh, wol, DD * DD / 4);

    // 3. QKV projection -> bf16 hi/lo output
    {
        dim3 grid(D3 / 128, BT / 128);
        gemm3<<<grid, 128, GEMM_SMEM_BYTES>>>(xnh, xnl, wqh, wql, nullptr, qh, ql, D3);
    }

    // 4. Causal attention (HMMA flash v5, cp.async double-buffered K/V)
    {
        dim3 grid(TT / 64, NB * HH);
        attn_hmma<<<grid, 128, ATTN_SMEM_BYTES>>>();
    }

    // 5. Output projection (fp32 out)
    {
        dim3 grid(DD / 128, BT / 128);
        gemm3<<<grid, 128, GEMM_SMEM_BYTES>>>(cxh, cxl, woh, wol, out, nullptr, nullptr, DD);
    }
}

// round 16
// speedup vs baseline: 1.8369x; 1.2059x over previous
#include <cuda_runtime.h>
#include <cuda_bf16.h>
#include <math.h>
#include <stdint.h>

// Problem constants
#define NB   4
#define TT   2048
#define DD   1024
#define HH   16
#define DHD  64
#define BT   (NB * TT)          // 8192 rows
#define D3   (3 * DD)           // 3072

// ---------------------------------------------------------------------------
// Scratch (no cudaMalloc allowed — device globals)
// ---------------------------------------------------------------------------
__device__ float g_xn[BT * DD];                            // LN output (tf32-rounded fp32)
__device__ float g_wqt[D3 * DD], g_wot[DD * DD];           // weights (tf32-rounded fp32)
__device__ float g_ctx[BT * DD];                           // attn output (tf32-rounded fp32)
__device__ __nv_bfloat16 g_qh[BT * D3], g_ql[BT * D3];     // QKV bf16 hi/lo (for attention)

// ---------------------------------------------------------------------------
// PTX helpers
// ---------------------------------------------------------------------------
#define MMA16816(Cacc, Afrag, Bfrag) \
    asm volatile( \
        "mma.sync.aligned.m16n8k16.row.col.f32.bf16.bf16.f32 " \
        "{%0,%1,%2,%3}, {%4,%5,%6,%7}, {%8,%9}, {%0,%1,%2,%3};" \
        : "+f"((Cacc)[0]), "+f"((Cacc)[1]), "+f"((Cacc)[2]), "+f"((Cacc)[3]) \
        : "r"((Afrag)[0]), "r"((Afrag)[1]), "r"((Afrag)[2]), "r"((Afrag)[3]), \
          "r"((Bfrag)[0]), "r"((Bfrag)[1]))

#define MMA1688TF(Cacc, Afrag, Bfrag) \
    asm volatile( \
        "mma.sync.aligned.m16n8k8.row.col.f32.tf32.tf32.f32 " \
        "{%0,%1,%2,%3}, {%4,%5,%6,%7}, {%8,%9}, {%0,%1,%2,%3};" \
        : "+f"((Cacc)[0]), "+f"((Cacc)[1]), "+f"((Cacc)[2]), "+f"((Cacc)[3]) \
        : "r"((Afrag)[0]), "r"((Afrag)[1]), "r"((Afrag)[2]), "r"((Afrag)[3]), \
          "r"((Bfrag)[0]), "r"((Bfrag)[1]))

#define CP16(saddr, gptr) \
    asm volatile("cp.async.cg.shared.global [%0], [%1], 16;" :: "r"(saddr), "l"(gptr))
#define CP_COMMIT() asm volatile("cp.async.commit_group;" ::: "memory")

#define LDSMT_X2(r, a) \
    asm volatile("ldmatrix.sync.aligned.m8n8.x2.trans.shared.b16 {%0,%1}, [%2];" \
                 : "=r"((r)[0]), "=r"((r)[1]) : "r"(a))

__device__ __forceinline__ uint32_t sptr(const void* p) {
    return (uint32_t)__cvta_generic_to_shared(p);
}

__device__ __forceinline__ float tf32r(float x) {
    uint32_t r;
    asm("cvt.rna.tf32.f32 %0, %1;" : "=r"(r) : "f"(x));
    return __uint_as_float(r);
}

__device__ __forceinline__ void split2(float a, float b, uint32_t& hi, uint32_t& lo) {
    __nv_bfloat16 ha = __float2bfloat16(a), hb = __float2bfloat16(b);
    __nv_bfloat16 la = __float2bfloat16(a - __bfloat162float(ha));
    __nv_bfloat16 lb = __float2bfloat16(b - __bfloat162float(hb));
    __nv_bfloat162 th = __halves2bfloat162(ha, hb);
    __nv_bfloat162 tl = __halves2bfloat162(la, lb);
    hi = *reinterpret_cast<uint32_t*>(&th);
    lo = *reinterpret_cast<uint32_t*>(&tl);
}

// ---------------------------------------------------------------------------
// LayerNorm: one block (256 threads) per row; writes tf32-rounded fp32
// ---------------------------------------------------------------------------
__global__ void __launch_bounds__(256) ln_kernel(const float* __restrict__ x,
                                                 const float* __restrict__ gamma,
                                                 const float* __restrict__ beta) {
    int row = blockIdx.x;
    int tid = threadIdx.x;
    __shared__ float red[2][8];

    const float4* xr = (const float4*)(x + (size_t)row * DD);
    float4 xv = xr[tid];
    float s  = xv.x + xv.y + xv.z + xv.w;
    float s2 = xv.x * xv.x + xv.y * xv.y + xv.z * xv.z + xv.w * xv.w;

    #pragma unroll
    for (int o = 16; o > 0; o >>= 1) {
        s  += __shfl_xor_sync(0xffffffffu, s, o);
        s2 += __shfl_xor_sync(0xffffffffu, s2, o);
    }
    if ((tid & 31) == 0) { red[0][tid >> 5] = s; red[1][tid >> 5] = s2; }
    __syncthreads();
    if (tid < 32) {
        float a = (tid < 8) ? red[0][tid] : 0.f;
        float b = (tid < 8) ? red[1][tid] : 0.f;
        #pragma unroll
        for (int o = 4; o > 0; o >>= 1) {
            a += __shfl_xor_sync(0xffffffffu, a, o);
            b += __shfl_xor_sync(0xffffffffu, b, o);
        }
        if (tid == 0) { red[0][0] = a * (1.f / DD); red[1][0] = b * (1.f / DD); }
    }
    __syncthreads();

    float mu   = red[0][0];
    float var  = red[1][0] - mu * mu;
    float rstd = rsqrtf(var + 1e-5f);

    float4 g  = ((const float4*)gamma)[tid];
    float4 bb = ((const float4*)beta)[tid];
    float4 y;
    y.x = tf32r((xv.x - mu) * rstd * g.x + bb.x);
    y.y = tf32r((xv.y - mu) * rstd * g.y + bb.y);
    y.z = tf32r((xv.z - mu) * rstd * g.z + bb.z);
    y.w = tf32r((xv.w - mu) * rstd * g.w + bb.w);
    ((float4*)(g_xn + (size_t)row * DD))[tid] = y;
}

// ---------------------------------------------------------------------------
// fp32 -> tf32-rounded fp32 (weights)
// ---------------------------------------------------------------------------
__global__ void __launch_bounds__(256) tf32cvt_kernel(const float* __restrict__ src,
                                                      float* __restrict__ dst, int n4) {
    int i = blockIdx.x * blockDim.x + threadIdx.x;
    if (i >= n4) return;
    float4 v = ((const float4*)src)[i];
    v.x = tf32r(v.x); v.y = tf32r(v.y); v.z = tf32r(v.z); v.w = tf32r(v.w);
    ((float4*)dst)[i] = v;
}

// ---------------------------------------------------------------------------
// TF32 GEMM: C[M,Ntot] = A[M,K] @ B[Ntot,K]^T, single pass (operands
// pre-rounded to tf32). CTA 128x128, 128 threads, warp tile 64x64,
// 2-stage cp.async pipeline, 2 CTAs/SM.
// Epilogue: fp32 to Cf if non-null, else bf16 hi/lo split to Chi/Clo.
// ---------------------------------------------------------------------------
#define SPADF 36
#define FTILE_ELEMS (128 * SPADF)                  // 4608 floats per array
#define GEMM_SMEM_BYTES (2 * 2 * FTILE_ELEMS * 4)  // 2 stages x (A,B) = 73728 B
#define NCHUNK (DD / 32)

#define FTILE(s, arr) (fsm + (size_t)((s) * 2 + (arr)) * FTILE_ELEMS)

__global__ void __launch_bounds__(128, 2) gemm_tf32(const float* __restrict__ A,
                                                    const float* __restrict__ B,
                                                    float* __restrict__ Cf,
                                                    __nv_bfloat16* __restrict__ Chi,
                                                    __nv_bfloat16* __restrict__ Clo,
                                                    int Ntot) {
    extern __shared__ __align__(16) float fsm[];

    int tid = threadIdx.x;
    int wid = tid >> 5, lid = tid & 31;
    int wm = wid >> 1, wn = wid & 1;
    int g = lid >> 2, t = lid & 3;
    int bm = blockIdx.y * 128;
    int bn = blockIdx.x * 128;

    float acc[4][8][4];
    #pragma unroll
    for (int i = 0; i < 4; i++)
        #pragma unroll
        for (int j = 0; j < 8; j++)
            #pragma unroll
            for (int r = 0; r < 4; r++) acc[i][j][r] = 0.f;

    #define GISSUE(s, kc) do { \
        float* tA = FTILE(s, 0); \
        float* tB = FTILE(s, 1); \
        _Pragma("unroll") \
        for (int c = 0; c < 8; c++) { \
            int idx = tid + c * 128; \
            int row = idx >> 3, c4 = (idx & 7) * 4; \
            size_t ga = (size_t)(bm + row) * DD + (kc) + c4; \
            size_t gb = (size_t)(bn + row) * DD + (kc) + c4; \
            CP16(sptr(tA + row * SPADF + c4), A + ga); \
            CP16(sptr(tB + row * SPADF + c4), B + gb); \
        } \
        CP_COMMIT(); \
    } while (0)

    GISSUE(0, 0);

    for (int ch = 0; ch < NCHUNK; ch++) {
        int cur = ch & 1;
        if (ch + 1 < NCHUNK) {
            GISSUE((ch + 1) & 1, (ch + 1) * 32);
            asm volatile("cp.async.wait_group 1;" ::: "memory");
        } else {
            asm volatile("cp.async.wait_group 0;" ::: "memory");
        }
        __syncthreads();

        const float* sA = FTILE(cur, 0);
        const float* sB = FTILE(cur, 1);

        #pragma unroll
        for (int ks = 0; ks < 4; ks++) {
            int kb = ks * 8;
            uint32_t a[4][4], b[8][2];
            #pragma unroll
            for (int i = 0; i < 4; i++) {
                int m0 = wm * 64 + i * 16;
                a[i][0] = __float_as_uint(sA[(m0 + g) * SPADF + kb + t]);
                a[i][1] = __float_as_uint(sA[(m0 + 8 + g) * SPADF + kb + t]);
                a[i][2] = __float_as_uint(sA[(m0 + g) * SPADF + kb + t + 4]);
                a[i][3] = __float_as_uint(sA[(m0 + 8 + g) * SPADF + kb + t + 4]);
            }
            #pragma unroll
            for (int j = 0; j < 8; j++) {
                int n0 = wn * 64 + j * 8;
                b[j][0] = __float_as_uint(sB[(n0 + g) * SPADF + kb + t]);
                b[j][1] = __float_as_uint(sB[(n0 + g) * SPADF + kb + t + 4]);
            }
            #pragma unroll
            for (int i = 0; i < 4; i++)
                #pragma unroll
                for (int j = 0; j < 8; j++)
                    MMA1688TF(acc[i][j], a[i], b[j]);
        }
        __syncthreads();
    }

    if (Cf) {
        #pragma unroll
        for (int i = 0; i < 4; i++) {
            int r0 = bm + wm * 64 + i * 16 + g;
            #pragma unroll
            for (int j = 0; j < 8; j++) {
                int c0 = bn + wn * 64 + j * 8 + 2 * t;
                *(float2*)&Cf[(size_t)r0 * Ntot + c0]       = make_float2(acc[i][j][0], acc[i][j][1]);
                *(float2*)&Cf[(size_t)(r0 + 8) * Ntot + c0] = make_float2(acc[i][j][2], acc[i][j][3]);
            }
        }
    } else {
        #pragma unroll
        for (int i = 0; i < 4; i++) {
            int r0 = bm + wm * 64 + i * 16 + g;
            #pragma unroll
            for (int j = 0; j < 8; j++) {
                int c0 = bn + wn * 64 + j * 8 + 2 * t;
                uint32_t hA, lA, hB, lB;
                split2(acc[i][j][0], acc[i][j][1], hA, lA);
                split2(acc[i][j][2], acc[i][j][3], hB, lB);
                *(uint32_t*)&Chi[(size_t)r0 * Ntot + c0]       = hA;
                *(uint32_t*)&Clo[(size_t)r0 * Ntot + c0]       = lA;
                *(uint32_t*)&Chi[(size_t)(r0 + 8) * Ntot + c0] = hB;
                *(uint32_t*)&Clo[(size_t)(r0 + 8) * Ntot + c0] = lB;
            }
        }
    }
}

// ---------------------------------------------------------------------------
// HMMA flash attention (causal), bf16x3 splits (R13-proven body).
// Epilogue writes tf32-rounded fp32 ctx for the tf32 out-projection.
// 128 threads (4 warps x 16 q-rows), key tiles of 64, 2 CTAs/SM.
// ---------------------------------------------------------------------------
#define APAD 72

__global__ void __launch_bounds__(128, 2) attn_hmma() {
    int qt  = gridDim.x - 1 - blockIdx.x;   // heavy tiles first
    int bh  = blockIdx.y;
    int b   = bh >> 4;
    int h   = bh & 15;
    int tid = threadIdx.x;
    int w   = tid >> 5, lid = tid & 31;
    int g   = lid >> 2, t = lid & 3;

    __shared__ __align__(16) uint16_t Kh[64][APAD], Kl[64][APAD];
    __shared__ __align__(16) uint16_t Vh[64][APAD], Vl[64][APAD];   // V row-major [key][d]

    int moff = (lid & 7) + ((lid >> 3) & 1) * 8;

    // ---- Q fragments straight from gmem (invariant across key tiles)
    uint32_t qh[4][4], ql[4][4];
    {
        const __nv_bfloat16* qbh = g_qh + (size_t)(b * TT + qt * 64 + w * 16) * D3 + h * 192;
        const __nv_bfloat16* qbl = g_ql + (size_t)(b * TT + qt * 64 + w * 16) * D3 + h * 192;
        #pragma unroll
        for (int ks = 0; ks < 4; ks++) {
            int kb = ks * 16;
            qh[ks][0] = *(const uint32_t*)(qbh + (size_t)g * D3 + kb + 2 * t);
            qh[ks][1] = *(const uint32_t*)(qbh + (size_t)(8 + g) * D3 + kb + 2 * t);
            qh[ks][2] = *(const uint32_t*)(qbh + (size_t)g * D3 + kb + 8 + 2 * t);
            qh[ks][3] = *(const uint32_t*)(qbh + (size_t)(8 + g) * D3 + kb + 8 + 2 * t);
            ql[ks][0] = *(const uint32_t*)(qbl + (size_t)g * D3 + kb + 2 * t);
            ql[ks][1] = *(const uint32_t*)(qbl + (size_t)(8 + g) * D3 + kb + 2 * t);
            ql[ks][2] = *(const uint32_t*)(qbl + (size_t)g * D3 + kb + 8 + 2 * t);
            ql[ks][3] = *(const uint32_t*)(qbl + (size_t)(8 + g) * D3 + kb + 8 + 2 * t);
        }
    }

    float oacc[8][4];
    #pragma unroll
    for (int c = 0; c < 8; c++)
        #pragma unroll
        for (int r = 0; r < 4; r++) oacc[c][r] = 0.f;
    float m0 = -1e30f, m1 = -1e30f, l0 = 0.f, l1 = 0.f;

    int ntiles = qt + 1;
    for (int kt = 0; kt < ntiles; kt++) {
        __syncthreads();
        {
            int r = tid >> 1, half = tid & 1;
            size_t base = (size_t)(b * TT + kt * 64 + r) * D3 + h * 192;
            const uint4* kh4 = (const uint4*)(g_qh + base + 64 + half * 32);
            const uint4* kl4 = (const uint4*)(g_ql + base + 64 + half * 32);
            const uint4* vh4 = (const uint4*)(g_qh + base + 128 + half * 32);
            const uint4* vl4 = (const uint4*)(g_ql + base + 128 + half * 32);
            #pragma unroll
            for (int j = 0; j < 4; j++) {
                *(uint4*)&Kh[r][half * 32 + j * 8] = kh4[j];
                *(uint4*)&Kl[r][half * 32 + j * 8] = kl4[j];
                *(uint4*)&Vh[r][half * 32 + j * 8] = vh4[j];
                *(uint4*)&Vl[r][half * 32 + j * 8] = vl4[j];
            }
        }
        __syncthreads();

        float sf[8][4];
        #pragma unroll
        for (int c = 0; c < 8; c++)
            #pragma unroll
            for (int r = 0; r < 4; r++) sf[c][r] = 0.f;

        #pragma unroll
        for (int ks = 0; ks < 4; ks++) {
            int kb = ks * 16;
            #pragma unroll
            for (int c = 0; c < 8; c++) {
                uint32_t bhf[2], blf[2];
                bhf[0] = *(const uint32_t*)&Kh[c * 8 + g][kb + 2 * t];
                bhf[1] = *(const uint32_t*)&Kh[c * 8 + g][kb + 8 + 2 * t];
                blf[0] = *(const uint32_t*)&Kl[c * 8 + g][kb + 2 * t];
                blf[1] = *(const uint32_t*)&Kl[c * 8 + g][kb + 8 + 2 * t];
                MMA16816(sf[c], qh[ks], bhf);
                MMA16816(sf[c], qh[ks], blf);
                MMA16816(sf[c], ql[ks], bhf);
            }
        }

        #pragma unroll
        for (int c = 0; c < 8; c++) {
            sf[c][0] *= 0.125f; sf[c][1] *= 0.125f;
            sf[c][2] *= 0.125f; sf[c][3] *= 0.125f;
        }

        if (kt == qt) {
            int colb = kt * 64 + 2 * t;
            int row0 = qt * 64 + w * 16 + g;
            #pragma unroll
            for (int c = 0; c < 8; c++) {
                int col = colb + c * 8;
                if (col     > row0)     sf[c][0] = -1e30f;
                if (col + 1 > row0)     sf[c][1] = -1e30f;
                if (col     > row0 + 8) sf[c][2] = -1e30f;
                if (col + 1 > row0 + 8) sf[c][3] = -1e30f;
            }
        }

        float rm0 = -1e30f, rm1 = -1e30f;
        #pragma unroll
        for (int c = 0; c < 8; c++) {
            rm0 = fmaxf(rm0, fmaxf(sf[c][0], sf[c][1]));
            rm1 = fmaxf(rm1, fmaxf(sf[c][2], sf[c][3]));
        }
        rm0 = fmaxf(rm0, __shfl_xor_sync(0xffffffffu, rm0, 1));
        rm0 = fmaxf(rm0, __shfl_xor_sync(0xffffffffu, rm0, 2));
        rm1 = fmaxf(rm1, __shfl_xor_sync(0xffffffffu, rm1, 1));
        rm1 = fmaxf(rm1, __shfl_xor_sync(0xffffffffu, rm1, 2));

        float mn0 = fmaxf(m0, rm0), mn1 = fmaxf(m1, rm1);
        float corr0 = __expf(m0 - mn0), corr1 = __expf(m1 - mn1);
        l0 *= corr0; l1 *= corr1;
        #pragma unroll
        for (int c = 0; c < 8; c++) {
            oacc[c][0] *= corr0; oacc[c][1] *= corr0;
            oacc[c][2] *= corr1; oacc[c][3] *= corr1;
        }

        uint32_t phA[8], phB[8], plA[8], plB[8];
        float rs0 = 0.f, rs1 = 0.f;
        #pragma unroll
        for (int c = 0; c < 8; c++) {
            float p0 = __expf(sf[c][0] - mn0);
            float p1 = __expf(sf[c][1] - mn0);
            float p2 = __expf(sf[c][2] - mn1);
            float p3 = __expf(sf[c][3] - mn1);
            rs0 += p0 + p1; rs1 += p2 + p3;
            split2(p0, p1, phA[c], plA[c]);
            split2(p2, p3, phB[c], plB[c]);
        }
        rs0 += __shfl_xor_sync(0xffffffffu, rs0, 1);
        rs0 += __shfl_xor_sync(0xffffffffu, rs0, 2);
        rs1 += __shfl_xor_sync(0xffffffffu, rs1, 1);
        rs1 += __shfl_xor_sync(0xffffffffu, rs1, 2);
        l0 += rs0; l1 += rs1;
        m0 = mn0; m1 = mn1;

        #pragma unroll
        for (int j = 0; j < 4; j++) {
            uint32_t a_h[4] = {phA[2 * j], phB[2 * j], phA[2 * j + 1], phB[2 * j + 1]};
            uint32_t a_l[4] = {plA[2 * j], plB[2 * j], plA[2 * j + 1], plB[2 * j + 1]};
            int kb = j * 16;
            #pragma unroll
            for (int c = 0; c < 8; c++) {
                uint32_t vh[2], vl[2];
                LDSMT_X2(vh, sptr(&Vh[kb + moff][c * 8]));
                LDSMT_X2(vl, sptr(&Vl[kb + moff][c * 8]));
                MMA16816(oacc[c], a_h, vh);
                MMA16816(oacc[c], a_h, vl);
                MMA16816(oacc[c], a_l, vh);
            }
        }
    }

    // ---- epilogue: divide by l, tf32-round, write fp32 ctx
    float il0 = 1.f / l0, il1 = 1.f / l1;
    int row0 = b * TT + qt * 64 + w * 16 + g;
    #pragma unroll
    for (int c = 0; c < 8; c++) {
        int col = h * DHD + c * 8 + 2 * t;
        *(float2*)&g_ctx[(size_t)row0 * DD + col] =
            make_float2(tf32r(oacc[c][0] * il0), tf32r(oacc[c][1] * il0));
        *(float2*)&g_ctx[(size_t)(row0 + 8) * DD + col] =
            make_float2(tf32r(oacc[c][2] * il1), tf32r(oacc[c][3] * il1));
    }
}

// ---------------------------------------------------------------------------
// Launch
// ---------------------------------------------------------------------------
extern "C" void kernel_launch(void* const* d_in, const int* in_sizes, int n_in,
                              void* d_out, int out_size) {
    const float* x     = (const float*)d_in[0];
    const float* gamma = (const float*)d_in[1];
    const float* beta  = (const float*)d_in[2];
    const float* w_qkv = (const float*)d_in[3];   // [3072, 1024]
    const float* w_o   = (const float*)d_in[4];   // [1024, 1024]
    float* out = (float*)d_out;                   // [8192, 1024]

    float *xn, *wqt, *wot, *ctx;
    __nv_bfloat16 *qh, *ql;
    cudaGetSymbolAddress((void**)&xn,  g_xn);
    cudaGetSymbolAddress((void**)&wqt, g_wqt);
    cudaGetSymbolAddress((void**)&wot, g_wot);
    cudaGetSymbolAddress((void**)&ctx, g_ctx);
    cudaGetSymbolAddress((void**)&qh,  g_qh);
    cudaGetSymbolAddress((void**)&ql,  g_ql);

    static int attr_set = 0;
    if (!attr_set) {
        cudaFuncSetAttribute(gemm_tf32, cudaFuncAttributeMaxDynamicSharedMemorySize,
                             GEMM_SMEM_BYTES);
        attr_set = 1;
    }

    // 1. LayerNorm -> tf32-rounded fp32
    ln_kernel<<<BT, 256>>>(x, gamma, beta);

    // 2. Weight tf32 rounding
    tf32cvt_kernel<<<(D3 * DD / 4 + 255) / 256, 256>>>(w_qkv, wqt, D3 * DD / 4);
    tf32cvt_kernel<<<(DD * DD / 4 + 255) / 256, 256>>>(w_o, wot, DD * DD / 4);

    // 3. QKV projection (tf32 single-pass) -> bf16 hi/lo output for attention
    {
        dim3 grid(D3 / 128, BT / 128);
        gemm_tf32<<<grid, 128, GEMM_SMEM_BYTES>>>(xn, wqt, nullptr, qh, ql, D3);
    }

    // 4. Causal attention (bf16x3 HMMA flash) -> tf32-rounded fp32 ctx
    {
        dim3 grid(TT / 64, NB * HH);
        attn_hmma<<<grid, 128>>>();
    }

    // 5. Output projection (tf32 single-pass, fp32 out)
    {
        dim3 grid(DD / 128, BT / 128);
        gemm_tf32<<<grid, 128, GEMM_SMEM_BYTES>>>(ctx, wot, out, nullptr, nullptr, DD);
    }
}